// round 16
// baseline (speedup 1.0000x reference)
#include <cuda_runtime.h>
#include <cuda_bf16.h>
#include <math.h>
#include <stdint.h>

#define BB 64
#define KB 8
#define RR 512
#define HH 1024
#define VV 400
#define V1 401
#define LL 13
#define G4 4096
#define NP 1000
#define SK 4

typedef unsigned long long ull;

// ---------------- persistent scratch -----------------------------------------
__device__ float d_ct[2][RR*HH];
__device__ float d_Gmx[2][RR];
__device__ float d_logp[2][RR];
__device__ int   d_prev[RR];
__device__ int   d_order[RR];
__device__ float d_samples[2][RR*LL];
__device__ float d_outputs[2][RR*LL];
__device__ float d_entplot[BB];
__device__ float d_entelem[BB];
__device__ float d_xW2[BB*G4];
__device__ float d_E[V1*128];
__device__ float d_Gt[V1*G4];
__device__ float d_Gt2[V1*G4];
__device__ float d_lu[NP];
__device__ __nv_bfloat16 d_w2b[2][G4*HH];
__device__ __nv_bfloat16 d_wf2b[2][HH*HH];
__device__ __nv_bfloat16 d_wo2b[2][512*HH];
__device__ __nv_bfloat16 d_h2b[2][RR*HH];
__device__ float d_graw[RR*G4];
__device__ float d_fc1p[SK][RR*HH];
__device__ float d_lpp[SK][RR*VV];
__device__ float d_lpn[RR*VV];
__device__ float d_gm[RR*VV];
__device__ float d_entrow[RR];
__device__ float d_phik[2][BB*KB];
__device__ float d_entbeams[2][BB*KB];
__device__ float d_Ts[BB*KB*NP];
__device__ float d_lseI[BB];
__device__ float d_lseIs[BB*KB];
__device__ float d_lseSS[BB*28];
__device__ float d_logRs[BB*KB];
__device__ float d_logRss[BB*KB*KB];

// ---------------- helpers ------------------------------------------------------
__device__ __forceinline__ float sigmoidf(float x){ return 1.f/(1.f+expf(-x)); }

__device__ __forceinline__ float log1mexp(float x){
    x = fminf(x, -1e-38f);
    if (x > -0.6931472f) return logf(-expm1f(x));
    return log1pf(-expf(x));
}
__device__ __forceinline__ uint32_t smem_u32(const void* p){
    uint32_t a;
    asm("{ .reg .u64 t; cvta.to.shared.u64 t, %1; cvt.u32.u64 %0, t; }" : "=r"(a) : "l"(p));
    return a;
}
__device__ __forceinline__ void ldsm_x4(unsigned* r, uint32_t addr){
    asm volatile("ldmatrix.sync.aligned.m8n8.x4.shared.b16 {%0,%1,%2,%3}, [%4];"
        : "=r"(r[0]), "=r"(r[1]), "=r"(r[2]), "=r"(r[3]) : "r"(addr));
}
__device__ __forceinline__ void ldsm_x2(unsigned* r, uint32_t addr){
    asm volatile("ldmatrix.sync.aligned.m8n8.x2.shared.b16 {%0,%1}, [%2];"
        : "=r"(r[0]), "=r"(r[1]) : "r"(addr));
}
__device__ __forceinline__ void mma_bf16(float* c, const unsigned* a, const unsigned* b){
    asm volatile("mma.sync.aligned.m16n8k16.row.col.f32.bf16.bf16.f32 "
        "{%0,%1,%2,%3}, {%4,%5,%6,%7}, {%8,%9}, {%0,%1,%2,%3};"
        : "+f"(c[0]), "+f"(c[1]), "+f"(c[2]), "+f"(c[3])
        : "r"(a[0]), "r"(a[1]), "r"(a[2]), "r"(a[3]), "r"(b[0]), "r"(b[1]));
}
__device__ __forceinline__ unsigned pkbf2(float a, float b){
    __nv_bfloat162 t; t.x = __float2bfloat16(a); t.y = __float2bfloat16(b);
    return *(unsigned*)&t;
}

// ---------------- init ----------------------------------------------------------
__global__ void init_kernel(const float* __restrict__ W_in_op,
                            const float* __restrict__ b_in_op){
    int idx = blockIdx.x*blockDim.x + threadIdx.x;
    int stride = gridDim.x*blockDim.x;
    for (int i = idx; i < RR;    i += stride){ d_Gmx[0][i]=0.f; d_logp[0][i]=0.f; }
    for (int i = idx; i < RR*LL; i += stride){ d_samples[0][i]=0.f; d_outputs[0][i]=0.f; }
    for (int i = idx; i < BB;    i += stride){ d_entplot[i]=0.f; d_entelem[i]=0.f; }
    for (int i = idx; i < NP;    i += stride) d_lu[i] = logf(((float)i + 0.5f)/(float)NP);
    for (int i = idx; i < V1*128; i += stride){
        int s = i >> 7, m = i & 127;
        d_E[i] = fmaxf(W_in_op[m*V1 + s] + b_in_op[m], 0.f);
    }
}

__global__ void reorder_whh(const float* __restrict__ W){
    int idx = blockIdx.x*blockDim.x + threadIdx.x;
    if (idx >= G4*HH) return;
    int c = idx >> 10, k = idx & 1023;
    int h = c >> 2, g = c & 3;
    float w = W[(size_t)(g*HH + h)*HH + k];
    __nv_bfloat16 b0 = __float2bfloat16(w);
    d_w2b[0][idx] = b0;
    d_w2b[1][idx] = __float2bfloat16(w - __bfloat162float(b0));
}

__global__ void split_fw(const float* __restrict__ W_fc1,
                         const float* __restrict__ W_out){
    int idx = blockIdx.x*blockDim.x + threadIdx.x;
    const int N1 = HH*HH;
    if (idx < N1){
        float w = W_fc1[idx];
        __nv_bfloat16 b0 = __float2bfloat16(w);
        d_wf2b[0][idx] = b0;
        d_wf2b[1][idx] = __float2bfloat16(w - __bfloat162float(b0));
    } else if (idx < N1 + 512*HH){
        int j = idx - N1;
        int row = j >> 10, k = j & 1023;
        float w = (row < VV) ? W_out[(size_t)row*HH + k] : 0.f;
        __nv_bfloat16 b0 = __float2bfloat16(w);
        d_wo2b[0][j] = b0;
        d_wo2b[1][j] = __float2bfloat16(w - __bfloat162float(b0));
    }
}

__global__ void permute_gates(const float* __restrict__ b_ih,
                              const float* __restrict__ b_hh){
    int idx = blockIdx.x*blockDim.x + threadIdx.x;
    if (idx >= (BB+V1)*G4) return;
    int row = idx / G4, c = idx - row*G4;
    int g = c >> 10, h = c & 1023;
    int dstc = 4*h + g;
    if (row < BB){
        size_t off = (size_t)row*G4 + c;
        float v = d_fc1p[0][off] + d_fc1p[1][off] + d_fc1p[2][off] + d_fc1p[3][off]
                + b_ih[c] + b_hh[c];
        d_xW2[row*G4 + dstc] = v;
    } else {
        d_Gt2[(size_t)(row-BB)*G4 + dstc] = d_Gt[(size_t)(row-BB)*G4 + c];
    }
}

// ---------------- setup GEMM (64x64x16 db, scalar) with K-split -------------------
__global__ void __launch_bounds__(256) gemm_db(
    const float* __restrict__ A, int lda,
    const float* __restrict__ B, int ldb,
    float* __restrict__ C, int ldc,
    int M, int N, int K, size_t zC)
{
    A += (size_t)blockIdx.z * K;
    B += (size_t)blockIdx.z * K;
    C += (size_t)blockIdx.z * zC;
    __shared__ float As[2][16][64+4];
    __shared__ float Bs[2][16][64+4];
    const int tid = threadIdx.x;
    const int row0 = blockIdx.y*64, col0 = blockIdx.x*64;
    const int arow = tid >> 2, ak = (tid & 3)*4;
    const int ty = tid >> 4, tx = tid & 15;

    const int ar = row0 + arow, br = col0 + arow;
    float4 a4 = make_float4(0,0,0,0), b4 = make_float4(0,0,0,0);
    if (ar < M) a4 = *(const float4*)(A + (size_t)ar*lda + ak);
    if (br < N) b4 = *(const float4*)(B + (size_t)br*ldb + ak);
    As[0][ak+0][arow]=a4.x; As[0][ak+1][arow]=a4.y; As[0][ak+2][arow]=a4.z; As[0][ak+3][arow]=a4.w;
    Bs[0][ak+0][arow]=b4.x; Bs[0][ak+1][arow]=b4.y; Bs[0][ak+2][arow]=b4.z; Bs[0][ak+3][arow]=b4.w;
    __syncthreads();

    float acc[4][4];
#pragma unroll
    for (int i=0;i<4;i++)
#pragma unroll
        for (int j=0;j<4;j++) acc[i][j]=0.f;

    const int NT = K/16;
    for (int it=0; it<NT; it++){
        int cur = it & 1;
        float4 a4n, b4n;
        if (it+1 < NT){
            int k0 = (it+1)*16;
            a4n = make_float4(0,0,0,0); b4n = make_float4(0,0,0,0);
            if (ar < M) a4n = *(const float4*)(A + (size_t)ar*lda + k0 + ak);
            if (br < N) b4n = *(const float4*)(B + (size_t)br*ldb + k0 + ak);
        }
#pragma unroll
        for (int kk=0; kk<16; kk++){
            float4 ra = *(const float4*)&As[cur][kk][ty*4];
            float4 rb = *(const float4*)&Bs[cur][kk][tx*4];
            float r[4]={ra.x,ra.y,ra.z,ra.w};
            float cb[4]={rb.x,rb.y,rb.z,rb.w};
#pragma unroll
            for (int i=0;i<4;i++)
#pragma unroll
                for (int j=0;j<4;j++) acc[i][j] = fmaf(r[i], cb[j], acc[i][j]);
        }
        if (it+1 < NT){
            int nb = cur^1;
            As[nb][ak+0][arow]=a4n.x; As[nb][ak+1][arow]=a4n.y; As[nb][ak+2][arow]=a4n.z; As[nb][ak+3][arow]=a4n.w;
            Bs[nb][ak+0][arow]=b4n.x; Bs[nb][ak+1][arow]=b4n.y; Bs[nb][ak+2][arow]=b4n.z; Bs[nb][ak+3][arow]=b4n.w;
        }
        __syncthreads();
    }
#pragma unroll
    for (int i=0;i<4;i++){
        int r = row0 + ty*4 + i;
        if (r >= M) continue;
#pragma unroll
        for (int j=0;j<4;j++){
            int c = col0 + tx*4 + j;
            if (c >= N) continue;
            C[(size_t)r*ldc + c] = acc[i][j];
        }
    }
}

// ---------------- generic bf16x2 HMMA NT GEMM (3 products) ------------------------
#define CH_TILE 6144
#define CH_BUF  (4*CH_TILE)
#define GM_DSMEM (2*CH_BUF)

template<int NCH, bool GUARD>
__global__ void __launch_bounds__(256) mma_nt(
    const __nv_bfloat16* __restrict__ A0, const __nv_bfloat16* __restrict__ A1,
    const __nv_bfloat16* __restrict__ B0, const __nv_bfloat16* __restrict__ B1,
    float* __restrict__ Cb, int ldc, size_t cstride)
{
    extern __shared__ char dsm[];
    const int tid = threadIdx.x, w = tid>>5, lane = tid&31;
    const int row0 = blockIdx.y*128, col0 = blockIdx.x*128;
    const int kb = blockIdx.z * (NCH*16);
    const int wr = w>>2, wc = w&3;
    const uint32_t dbase = smem_u32(dsm);
    float* C = Cb + blockIdx.z * cstride;

    const __nv_bfloat16* Asrc[2] = {A0, A1};
    const __nv_bfloat16* Bsrc[2] = {B0, B1};

    int ld_tile[4], ld_row[4], ld_half[4];
    const __nv_bfloat16* ld_src[4];
#pragma unroll
    for (int j=0;j<4;j++){
        int idx = tid + j*256;
        int t = idx >> 8, pos = idx & 255;
        int row = pos >> 1, half = pos & 1;
        ld_tile[j]=t; ld_row[j]=row; ld_half[j]=half;
        if (t < 2) ld_src[j] = Asrc[t]   + (size_t)(row0+row)*HH + kb + half*8;
        else       ld_src[j] = Bsrc[t-2] + (size_t)(col0+row)*HH + kb + half*8;
    }

    float acc[4][4][4];
#pragma unroll
    for (int mi=0;mi<4;mi++)
#pragma unroll
        for (int ni=0;ni<4;ni++)
#pragma unroll
            for (int e=0;e<4;e++) acc[mi][ni][e]=0.f;

    uint4 v[4];
#pragma unroll
    for (int j=0;j<4;j++) v[j] = *(const uint4*)(ld_src[j]);
    {
        char* bp = dsm;
#pragma unroll
        for (int j=0;j<4;j++)
            *(uint4*)(bp + ld_tile[j]*CH_TILE + ld_row[j]*48 + ld_half[j]*16) = v[j];
    }
    __syncthreads();

    const uint32_t a_lm = dbase + (wr*64 + (lane&15))*48 + (lane>>4)*16;
    const uint32_t b_lm = dbase + (wc*32 + (lane&7))*48 + ((lane>>3)&1)*16;

    for (int kc = 0; kc < NCH; kc++){
        if (kc+1 < NCH){
#pragma unroll
            for (int j=0;j<4;j++) v[j] = *(const uint4*)(ld_src[j] + (kc+1)*16);
        }
        const uint32_t bb = (kc&1)*CH_BUF;

        unsigned Bf[2][4][2];
#pragma unroll
        for (int s=0;s<2;s++)
#pragma unroll
            for (int ni=0;ni<4;ni++)
                ldsm_x2(Bf[s][ni], b_lm + bb + (2+s)*CH_TILE + ni*8*48);

#pragma unroll
        for (int s=0;s<2;s++){
            unsigned Af[4][4];
#pragma unroll
            for (int mi=0;mi<4;mi++)
                ldsm_x4(Af[mi], a_lm + bb + s*CH_TILE + mi*16*48);
            const int nb = (s==0) ? 2 : 1;
#pragma unroll
            for (int jb=0;jb<2;jb++){
                if (jb >= nb) break;
#pragma unroll
                for (int mi=0;mi<4;mi++)
#pragma unroll
                    for (int ni=0;ni<4;ni++)
                        mma_bf16(acc[mi][ni], Af[mi], Bf[jb][ni]);
            }
        }

        if (kc+1 < NCH){
            char* bp = dsm + ((kc+1)&1)*CH_BUF;
#pragma unroll
            for (int j=0;j<4;j++)
                *(uint4*)(bp + ld_tile[j]*CH_TILE + ld_row[j]*48 + ld_half[j]*16) = v[j];
        }
        __syncthreads();
    }

#pragma unroll
    for (int mi=0;mi<4;mi++)
#pragma unroll
        for (int ni=0;ni<4;ni++){
            int rl = wr*64 + mi*16 + (lane>>2);
            int cl = wc*32 + ni*8 + 2*(lane&3);
            if (GUARD && col0+cl >= ldc) continue;
            float2 p0 = make_float2(acc[mi][ni][0], acc[mi][ni][1]);
            float2 p1 = make_float2(acc[mi][ni][2], acc[mi][ni][3]);
            *(float2*)&C[(size_t)(row0+rl)*ldc   + col0 + cl] = p0;
            *(float2*)&C[(size_t)(row0+rl+8)*ldc + col0 + cl] = p1;
        }
}

// ---------------- out GEMM with fused hd ------------------------------------------
__global__ void __launch_bounds__(256) out_fused(const float* __restrict__ b_fc1){
    extern __shared__ char dsm[];
    const int tid = threadIdx.x, w = tid>>5, lane = tid&31;
    const int row0 = blockIdx.y*128, col0 = blockIdx.x*128;
    const int kb = blockIdx.z * 256;
    const int wr = w>>2, wc = w&3;
    const uint32_t dbase = smem_u32(dsm);
    float* C = d_lpp[blockIdx.z];

    const int arow_ = tid >> 1, half = tid & 1;
    const size_t aoffb = (size_t)(row0+arow_)*HH + kb + half*8;
    const __nv_bfloat16* bsrc0 = d_wo2b[0] + (size_t)(col0+arow_)*HH + kb + half*8;
    const __nv_bfloat16* bsrc1 = d_wo2b[1] + (size_t)(col0+arow_)*HH + kb + half*8;
    const uint32_t st_a = arow_*48 + half*16;

    auto computeA = [&](int kc, uint4 &lo, uint4 &hi){
        size_t off = aoffb + kc*16;
        int bix = kb + kc*16 + half*8;
        float x[8];
        {
            float4 p0=*(const float4*)&d_fc1p[0][off], p1=*(const float4*)&d_fc1p[1][off];
            float4 p2=*(const float4*)&d_fc1p[2][off], p3=*(const float4*)&d_fc1p[3][off];
            float4 bf=*(const float4*)&b_fc1[bix];
            x[0]=fmaxf(p0.x+p1.x+p2.x+p3.x+bf.x,0.f);
            x[1]=fmaxf(p0.y+p1.y+p2.y+p3.y+bf.y,0.f);
            x[2]=fmaxf(p0.z+p1.z+p2.z+p3.z+bf.z,0.f);
            x[3]=fmaxf(p0.w+p1.w+p2.w+p3.w+bf.w,0.f);
        }
        {
            float4 p0=*(const float4*)&d_fc1p[0][off+4], p1=*(const float4*)&d_fc1p[1][off+4];
            float4 p2=*(const float4*)&d_fc1p[2][off+4], p3=*(const float4*)&d_fc1p[3][off+4];
            float4 bf=*(const float4*)&b_fc1[bix+4];
            x[4]=fmaxf(p0.x+p1.x+p2.x+p3.x+bf.x,0.f);
            x[5]=fmaxf(p0.y+p1.y+p2.y+p3.y+bf.y,0.f);
            x[6]=fmaxf(p0.z+p1.z+p2.z+p3.z+bf.z,0.f);
            x[7]=fmaxf(p0.w+p1.w+p2.w+p3.w+bf.w,0.f);
        }
        unsigned lo_[4], hi_[4];
#pragma unroll
        for (int e=0;e<4;e++){
            float a = x[2*e], b = x[2*e+1];
            __nv_bfloat16 la = __float2bfloat16(a), lb = __float2bfloat16(b);
            lo_[e] = pkbf2(a, b);
            hi_[e] = pkbf2(a - __bfloat162float(la), b - __bfloat162float(lb));
        }
        lo = make_uint4(lo_[0], lo_[1], lo_[2], lo_[3]);
        hi = make_uint4(hi_[0], hi_[1], hi_[2], hi_[3]);
    };

    float acc[4][4][4];
#pragma unroll
    for (int mi=0;mi<4;mi++)
#pragma unroll
        for (int ni=0;ni<4;ni++)
#pragma unroll
            for (int e=0;e<4;e++) acc[mi][ni][e]=0.f;

    uint4 aLo, aHi, vB0, vB1;
    computeA(0, aLo, aHi);
    vB0 = *(const uint4*)bsrc0;
    vB1 = *(const uint4*)bsrc1;
    {
        char* bp = dsm;
        *(uint4*)(bp + 0*CH_TILE + st_a) = aLo;
        *(uint4*)(bp + 1*CH_TILE + st_a) = aHi;
        *(uint4*)(bp + 2*CH_TILE + st_a) = vB0;
        *(uint4*)(bp + 3*CH_TILE + st_a) = vB1;
    }
    __syncthreads();

    const uint32_t a_lm = dbase + (wr*64 + (lane&15))*48 + (lane>>4)*16;
    const uint32_t b_lm = dbase + (wc*32 + (lane&7))*48 + ((lane>>3)&1)*16;

    for (int kc = 0; kc < 16; kc++){
        if (kc+1 < 16){
            computeA(kc+1, aLo, aHi);
            vB0 = *(const uint4*)(bsrc0 + (kc+1)*16);
            vB1 = *(const uint4*)(bsrc1 + (kc+1)*16);
        }
        const uint32_t bb = (kc&1)*CH_BUF;

        unsigned Bf[2][4][2];
#pragma unroll
        for (int s=0;s<2;s++)
#pragma unroll
            for (int ni=0;ni<4;ni++)
                ldsm_x2(Bf[s][ni], b_lm + bb + (2+s)*CH_TILE + ni*8*48);

#pragma unroll
        for (int s=0;s<2;s++){
            unsigned Af[4][4];
#pragma unroll
            for (int mi=0;mi<4;mi++)
                ldsm_x4(Af[mi], a_lm + bb + s*CH_TILE + mi*16*48);
            const int nb = (s==0) ? 2 : 1;
#pragma unroll
            for (int jb=0;jb<2;jb++){
                if (jb >= nb) break;
#pragma unroll
                for (int mi=0;mi<4;mi++)
#pragma unroll
                    for (int ni=0;ni<4;ni++)
                        mma_bf16(acc[mi][ni], Af[mi], Bf[jb][ni]);
            }
        }

        if (kc+1 < 16){
            char* bp = dsm + ((kc+1)&1)*CH_BUF;
            *(uint4*)(bp + 0*CH_TILE + st_a) = aLo;
            *(uint4*)(bp + 1*CH_TILE + st_a) = aHi;
            *(uint4*)(bp + 2*CH_TILE + st_a) = vB0;
            *(uint4*)(bp + 3*CH_TILE + st_a) = vB1;
        }
        __syncthreads();
    }

#pragma unroll
    for (int mi=0;mi<4;mi++)
#pragma unroll
        for (int ni=0;ni<4;ni++){
            int rl = wr*64 + mi*16 + (lane>>2);
            int cl = wc*32 + ni*8 + 2*(lane&3);
            if (col0+cl >= VV) continue;
            float2 p0 = make_float2(acc[mi][ni][0], acc[mi][ni][1]);
            float2 p1 = make_float2(acc[mi][ni][2], acc[mi][ni][3]);
            *(float2*)&C[(size_t)(row0+rl)*VV   + col0 + cl] = p0;
            *(float2*)&C[(size_t)(row0+rl+8)*VV + col0 + cl] = p1;
        }
}

// ---------------- LSTM elementwise -------------------------------------------------
__global__ void __launch_bounds__(256) lstm_elem(int t, int cur){
    const int r = blockIdx.x, tid = threadIdx.x;
    const int prv = cur^1;
    const int b = r & 63;
    int o, pv;
    if (t == 0){ o = r; pv = VV; } else { o = d_order[r]; pv = d_prev[r]; }
    const float4* gr = (const float4*)(d_graw + (size_t)o*G4);
    const float4* xw = (const float4*)(d_xW2 + (size_t)b*G4);
    const float4* gt = (const float4*)(d_Gt2 + (size_t)pv*G4);
    const float* cpf = d_ct[prv] + (size_t)o*HH;
    float* cf = d_ct[cur] + (size_t)r*HH;
#pragma unroll
    for (int q=0;q<4;q++){
        int u = tid + q*256;
        float4 g = (t==0) ? make_float4(0,0,0,0) : gr[u];
        float4 x = xw[u];
        float4 G = gt[u];
        float ig = g.x + x.x + G.x;
        float fg = g.y + x.y + G.y;
        float gg = g.z + x.z + G.z;
        float og = g.w + x.w + G.w;
        float cold = (t==0) ? 0.f : cpf[u];
        float cn = sigmoidf(fg)*cold + sigmoidf(ig)*tanhf(gg);
        float hn = sigmoidf(og)*tanhf(cn);
        cf[u] = cn;
        __nv_bfloat16 s0 = __float2bfloat16(hn);
        d_h2b[0][(size_t)r*HH + u] = s0;
        d_h2b[1][(size_t)r*HH + u] = __float2bfloat16(hn - __bfloat162float(s0));
    }
}

// ---------------- A1: per-row softmax + entropy + gumbel-with-max -----------------
__global__ void __launch_bounds__(128) rowsoft(const float* __restrict__ gu,
                                               const float* __restrict__ b_out,
                                               int t, int cur){
    const int r = blockIdx.x, tid = threadIdx.x;
    __shared__ float red[128];
    const size_t rb = (size_t)r*VV;

    float lv[4];
#pragma unroll
    for (int ii=0; ii<4; ii++){
        int v = tid + ii*128;
        lv[ii] = (v < VV)
            ? (d_lpp[0][rb+v] + d_lpp[1][rb+v] + d_lpp[2][rb+v] + d_lpp[3][rb+v] + b_out[v])
            : -INFINITY;
    }
    float m = fmaxf(fmaxf(lv[0],lv[1]), fmaxf(lv[2],lv[3]));
    red[tid] = m; __syncthreads();
    for (int off=64; off; off>>=1){ if (tid<off) red[tid]=fmaxf(red[tid],red[tid+off]); __syncthreads(); }
    m = red[0]; __syncthreads();

    float s = 0.f;
#pragma unroll
    for (int ii=0; ii<4; ii++){ int v = tid+ii*128; if (v < VV) s += expf(lv[ii]-m); }
    red[tid] = s; __syncthreads();
    for (int off=64; off; off>>=1){ if (tid<off) red[tid]+=red[tid+off]; __syncthreads(); }
    float lse = m + logf(red[0]); __syncthreads();

    float lpr = d_logp[cur][r];
    float Gr  = d_Gmx[cur][r];
    const float* u = gu + ((size_t)t*RR + r)*VV;
    float ent = 0.f, zm = -INFINITY;
    float gv[4];
#pragma unroll
    for (int ii=0; ii<4; ii++){
        int v = tid + ii*128;
        if (v >= VV){ gv[ii] = -INFINITY; continue; }
        float l = lv[ii]-lse;
        d_lpn[rb+v] = l;
        ent += l*expf(l);
        float gmb = -logf(-logf(u[v]*(1.f-2e-7f)+1e-7f));
        float gph = l + lpr + gmb;
        gv[ii] = gph;
        zm = fmaxf(zm, gph);
    }
    red[tid] = ent; __syncthreads();
    for (int off=64; off; off>>=1){ if (tid<off) red[tid]+=red[tid+off]; __syncthreads(); }
    if (tid==0) d_entrow[r] = red[0];
    __syncthreads();
    red[tid] = zm; __syncthreads();
    for (int off=64; off; off>>=1){ if (tid<off) red[tid]=fmaxf(red[tid],red[tid+off]); __syncthreads(); }
    float Z = red[0];
#pragma unroll
    for (int ii=0; ii<4; ii++){
        int v = tid + ii*128;
        if (v >= VV) continue;
        float gph = gv[ii];
        float vv = Gr - gph + log1mexp(gph - Z);
        d_gm[rb+v] = Gr - fmaxf(vv,0.f) - log1pf(expf(-fabsf(vv)));
    }
}

// ---------------- A2: top-k + gather + fused Ts precompute ------------------------
__global__ void __launch_bounds__(256) topsel(int t, int cur){
    __shared__ float cv_s[64];
    __shared__ int   ci_s[64];
    __shared__ float gvalS[KB], phiS_s[KB];
    __shared__ int   ordS[KB], snewS[KB];

    const int i = blockIdx.x, tid = threadIdx.x;
    const int lane = tid & 31, w = tid >> 5;
    const int r = w*BB + i;
    const size_t rb = (size_t)r*VV;
    const int ph = t & 1;

    float lv[13];
#pragma unroll
    for (int ii=0; ii<13; ii++){
        int v = lane + ii*32;
        lv[ii] = (v < VV && !(t==0 && w>0)) ? d_gm[rb+v] : -INFINITY;
    }

    for (int round=0; round<KB; round++){
        float bv = -INFINITY; int bi = 0x7fffffff;
#pragma unroll
        for (int ii=0; ii<13; ii++){
            int v = lane + ii*32;
            if (v >= VV) continue;
            float x = lv[ii]; int fi = w*VV + v;
            if (x > bv || (x == bv && fi < bi)){ bv = x; bi = fi; }
        }
#pragma unroll
        for (int off=16; off; off>>=1){
            float bv2 = __shfl_xor_sync(0xffffffffu, bv, off);
            int   bi2 = __shfl_xor_sync(0xffffffffu, bi, off);
            if (bv2 > bv || (bv2 == bv && bi2 < bi)){ bv = bv2; bi = bi2; }
        }
        int vwin = bi - w*VV;
        if (vwin >= 0 && vwin < VV && (vwin & 31) == lane) lv[vwin >> 5] = -INFINITY;
        if (lane == 0){ cv_s[w*KB + round] = bv; ci_s[w*KB + round] = bi; }
    }
    __syncthreads();

    if (w == 0){
        float c0 = cv_s[lane], c1 = cv_s[lane+32];
        int   i0 = ci_s[lane], i1 = ci_s[lane+32];
        for (int round=0; round<KB; round++){
            float bv; int bi;
            if (c0 > c1 || (c0 == c1 && i0 < i1)){ bv = c0; bi = i0; }
            else                                 { bv = c1; bi = i1; }
#pragma unroll
            for (int off=16; off; off>>=1){
                float bv2 = __shfl_xor_sync(0xffffffffu, bv, off);
                int   bi2 = __shfl_xor_sync(0xffffffffu, bi, off);
                if (bv2 > bv || (bv2 == bv && bi2 < bi)){ bv = bv2; bi = bi2; }
            }
            if (i0 == bi) c0 = -INFINITY;
            if (i1 == bi) c1 = -INFINITY;
            if (lane == 0){
                gvalS[round] = bv;
                ordS[round]  = bi / VV;
                snewS[round] = bi % VV;
            }
        }
    }
    __syncthreads();

    const int nxt = cur^1;
    for (int idx=tid; idx<KB*LL; idx+=256){
        int j = idx/LL, tt = idx - j*LL;
        if (tt == t) continue;
        int rn = j*BB+i, o = ordS[j]*BB+i;
        d_samples[nxt][rn*LL+tt] = d_samples[cur][o*LL+tt];
        d_outputs[nxt][rn*LL+tt] = d_outputs[cur][o*LL+tt];
    }
    if (tid < KB){
        int j = tid, rn = j*BB+i, o = ordS[j]*BB+i, sv = snewS[j];
        float lpv = d_lpn[(size_t)o*VV + sv];
        float nl  = d_logp[cur][o] + lpv;
        d_samples[nxt][rn*LL+t] = (float)sv;
        d_outputs[nxt][rn*LL+t] = lpv;
        d_logp[nxt][rn] = nl;
        d_Gmx[nxt][rn]  = gvalS[j];
        d_prev[rn]  = sv;
        d_order[rn] = o;
        d_phik[ph][i*KB+j]     = nl;
        d_entbeams[ph][i*KB+j] = d_entrow[o];
        phiS_s[j] = nl;
    }
    __syncthreads();

    // fused Ts precompute: warp w writes Ts row w
    {
        float p = expf(phiS_s[w]);
        float* dst = d_Ts + ((size_t)i*KB + w)*NP;
        for (int n = lane; n < NP; n += 32)
            dst[n] = log1mexp(p * d_lu[n]);
    }
}

// ---------------- warp LSE ---------------------------------------------------------
__device__ __forceinline__ float warpLSE(const float* __restrict__ base,
                                         const float* __restrict__ t1,
                                         const float* __restrict__ t2){
    int lane = threadIdx.x & 31;
    float m = -INFINITY, s = 0.f;
    for (int n = lane; n < NP; n += 32){
        float x = base[n];
        if (t1) x -= t1[n];
        if (t2) x -= t2[n];
        if (x > m){ s = s*expf(m-x) + 1.f; m = x; } else s += expf(x-m);
    }
#pragma unroll
    for (int off=16; off; off>>=1){
        float m2 = __shfl_xor_sync(0xffffffffu, m, off);
        float s2 = __shfl_xor_sync(0xffffffffu, s, off);
        float mm = fmaxf(m, m2);
        s = s*expf(m-mm) + s2*expf(m2-mm);
        m = mm;
    }
    return m + logf(s);
}

// ---------------- B2: distributed LSEs ---------------------------------------------
__global__ void __launch_bounds__(256) logR_lse(int ph){
    __shared__ float Ts_s[KB*NP];
    __shared__ float base_s[NP];
    const int g = blockIdx.x, i = blockIdx.y, tid = threadIdx.x;
    const int lane = tid & 31, w = tid >> 5;

    for (int idx = tid; idx < KB*NP; idx += 256)
        Ts_s[idx] = d_Ts[(size_t)i*KB*NP + idx];
    float pS = 0.f;
#pragma unroll
    for (int j=0;j<KB;j++) pS += expf(d_phik[ph][i*KB+j]);
    __syncthreads();
    for (int n = tid; n < NP; n += 256){
        float bs = -pS*d_lu[n];
#pragma unroll
        for (int j=0;j<KB;j++) bs += Ts_s[j*NP+n];
        base_s[n] = bs;
    }
    __syncthreads();

    const int q = g*8 + w;
    if (q < 37){
        const float *t1 = nullptr, *t2 = nullptr;
        int a = 0, b = 0;
        if (q >= 1 && q <= 8){ t1 = Ts_s + (q-1)*NP; }
        else if (q >= 9){
            int pp = q-9, rem = pp;
            while (rem >= 7 - a){ rem -= (7 - a); a++; }
            b = a + 1 + rem;
            t1 = Ts_s + a*NP; t2 = Ts_s + b*NP;
        }
        float res = warpLSE(base_s, t1, t2);
        if (lane == 0){
            if (q == 0)      d_lseI[i] = res;
            else if (q <= 8) d_lseIs[i*KB + q-1] = res;
            else             d_lseSS[i*28 + (q-9)] = res;
        }
    }
}

// ---------------- B3: finalize log_R + entropy accumulation ------------------------
__global__ void __launch_bounds__(32) logR_fin(int ph){
    const int i = blockIdx.x, tid = threadIdx.x;
    float logI = d_lseI[i];
    if (tid < KB) d_logRs[i*KB+tid] = d_lseIs[i*KB+tid] - logI;
    if (tid < 28){
        int a = 0, rem = tid;
        while (rem >= 7 - a){ rem -= (7 - a); a++; }
        int b = a + 1 + rem;
        float lss = d_lseSS[i*28+tid];
        d_logRss[i*64 + a*8 + b] = lss - d_lseIs[i*KB+a];
        d_logRss[i*64 + b*8 + a] = lss - d_lseIs[i*KB+b];
    }
    if (tid < KB) d_logRss[i*64 + tid*9] = 0.f;
    if (tid == 0){
        float Wsum = 0.f, ws = 0.f;
#pragma unroll
        for (int j=0;j<KB;j++){
            float wq = expf(d_phik[ph][i*KB+j] + d_lseIs[i*KB+j] - logI);
            Wsum += wq;
            ws   += wq * d_entbeams[ph][i*KB+j];
        }
        d_entplot[i] += ws;
        d_entelem[i] += ws / Wsum;
    }
}

// ---------------- output assembly ---------------------------------------------------
__global__ void finalize_kernel(float* __restrict__ out, int out_size){
    int idx = blockIdx.x*blockDim.x + threadIdx.x;
    if (idx >= out_size || idx >= 18560) return;
    const int FIN = LL & 1;
    if (idx < 6656){
        int i = idx/104, rem = idx%104, j = rem/13, tt = rem%13;
        out[idx] = d_outputs[FIN][(j*BB+i)*LL + tt];
    } else if (idx < 13312){
        int q = idx - 6656;
        int i = q/104, rem = q%104, j = rem/13, tt = rem%13;
        out[idx] = d_samples[FIN][(j*BB+i)*LL + tt];
    } else if (idx < 13376){
        out[idx] = d_entelem[idx-13312];
    } else if (idx < 13888){
        out[idx] = d_logRs[idx-13376];
    } else if (idx < 17984){
        out[idx] = d_logRss[idx-13888];
    } else if (idx < 18496){
        out[idx] = d_phik[(LL-1)&1][idx-17984];
    } else {
        out[idx] = d_entplot[idx-18496];
    }
}

// ---------------- host driver ---------------------------------------------------------
extern "C" void kernel_launch(void* const* d_in, const int* in_sizes, int n_in,
                              void* d_out, int out_size){
    const float* x_feat  = (const float*)d_in[0];
    const float* W_in_op = (const float*)d_in[1];
    const float* b_in_op = (const float*)d_in[2];
    const float* W_ih    = (const float*)d_in[3];
    const float* W_hh    = (const float*)d_in[4];
    const float* b_ih    = (const float*)d_in[5];
    const float* b_hh    = (const float*)d_in[6];
    const float* W_fc1   = (const float*)d_in[7];
    const float* b_fc1   = (const float*)d_in[8];
    const float* W_out   = (const float*)d_in[9];
    const float* b_out   = (const float*)d_in[10];
    const float* gu      = (const float*)d_in[11];
    (void)in_sizes; (void)n_in;

    void* tmp;
    cudaGetSymbolAddress(&tmp, d_E);     float* p_E   = (float*)tmp;
    cudaGetSymbolAddress(&tmp, d_Gt);    float* p_Gt  = (float*)tmp;
    cudaGetSymbolAddress(&tmp, d_h2b);   __nv_bfloat16* p_h2b = (__nv_bfloat16*)tmp;
    cudaGetSymbolAddress(&tmp, d_w2b);   __nv_bfloat16* p_w2b = (__nv_bfloat16*)tmp;
    cudaGetSymbolAddress(&tmp, d_wf2b);  __nv_bfloat16* p_wf  = (__nv_bfloat16*)tmp;
    cudaGetSymbolAddress(&tmp, d_graw);  float* p_graw = (float*)tmp;
    cudaGetSymbolAddress(&tmp, d_fc1p);  float* p_fc1p = (float*)tmp;

    static cudaStream_t s1 = nullptr, s2 = nullptr;
    static cudaEvent_t ev0=nullptr, evA=nullptr, evB=nullptr, evW=nullptr,
                       evE=nullptr, evEnd=nullptr;
    if (s1 == nullptr){
        cudaStreamCreateWithFlags(&s1, cudaStreamNonBlocking);
        cudaStreamCreateWithFlags(&s2, cudaStreamNonBlocking);
        cudaEventCreateWithFlags(&ev0, cudaEventDisableTiming);
        cudaEventCreateWithFlags(&evA, cudaEventDisableTiming);
        cudaEventCreateWithFlags(&evB, cudaEventDisableTiming);
        cudaEventCreateWithFlags(&evW, cudaEventDisableTiming);
        cudaEventCreateWithFlags(&evE, cudaEventDisableTiming);
        cudaEventCreateWithFlags(&evEnd, cudaEventDisableTiming);
        cudaFuncSetAttribute(mma_nt<64,false>, cudaFuncAttributeMaxDynamicSharedMemorySize, GM_DSMEM);
        cudaFuncSetAttribute(mma_nt<16,false>, cudaFuncAttributeMaxDynamicSharedMemorySize, GM_DSMEM);
        cudaFuncSetAttribute(out_fused, cudaFuncAttributeMaxDynamicSharedMemorySize, GM_DSMEM);
    }

    cudaEventRecord(ev0, 0);
    cudaStreamWaitEvent(s1, ev0, 0);
    cudaStreamWaitEvent(s2, ev0, 0);

    // s1: init (produces d_E, d_lu) then xW partials
    init_kernel<<<256,256,0,s1>>>(W_in_op, b_in_op);
    cudaEventRecord(evE, s1);
    gemm_db<<<dim3(64,1,SK),256,0,s1>>>(x_feat,1024, W_ih,1152,
                                        p_fc1p, G4, BB, G4, 256, (size_t)RR*HH);

    // s2: weight splits + Gt GEMM (needs d_E)
    reorder_whh<<<(G4*HH+255)/256, 256, 0, s2>>>(W_hh);
    split_fw<<<((HH*HH + 512*HH)+255)/256, 256, 0, s2>>>(W_fc1, W_out);
    cudaStreamWaitEvent(s2, evE, 0);
    gemm_db<<<dim3(64,7,1),256,0,s2>>>(p_E,128, W_ih+1024,1152,
                                       p_Gt, G4, V1, G4, 128, 0);
    cudaEventRecord(evW, s2);

    cudaStreamWaitEvent(s1, evW, 0);
    permute_gates<<<((BB+V1)*G4+255)/256,256,0,s1>>>(b_ih, b_hh);

    for (int t = 0; t < LL; t++){
        int cur = t & 1;
        const bool t0 = (t == 0);

        lstm_elem<<<RR,256,0,s1>>>(t, cur);

        if (t < LL-1){
            cudaEventRecord(evA, s1);
            cudaStreamWaitEvent(s2, evA, 0);
            if (t0)
                mma_nt<64,false><<<dim3(32,1,1),256,GM_DSMEM,s2>>>(
                    p_h2b, p_h2b + (size_t)RR*HH,
                    p_w2b, p_w2b + (size_t)G4*HH,
                    p_graw, G4, 0);
            else
                mma_nt<64,false><<<dim3(32,4,1),256,GM_DSMEM,s2>>>(
                    p_h2b, p_h2b + (size_t)RR*HH,
                    p_w2b, p_w2b + (size_t)G4*HH,
                    p_graw, G4, 0);
            cudaEventRecord(evB, s2);
        }

        // t=0: only batch rows [0,64) reachable by the masked top-k -> shrink grids
        mma_nt<16,false><<<dim3(8, t0?1:4, SK),256,GM_DSMEM,s1>>>(
            p_h2b, p_h2b + (size_t)RR*HH,
            p_wf,  p_wf  + (size_t)HH*HH,
            p_fc1p, HH, (size_t)RR*HH);
        out_fused<<<dim3(4, t0?1:4, SK),256,GM_DSMEM,s1>>>(b_fc1);
        rowsoft<<<t0?BB:RR,128,0,s1>>>(gu, b_out, t, cur);
        topsel<<<BB,256,0,s1>>>(t, cur);
        logR_lse<<<dim3(5,BB),256,0,s1>>>(cur);
        logR_fin<<<BB,32,0,s1>>>(cur);

        if (t < LL-1){
            cudaStreamWaitEvent(s1, evB, 0);
        }
    }

    finalize_kernel<<<(18560+255)/256,256,0,s1>>>((float*)d_out, out_size);
    cudaEventRecord(evEnd, s1);
    cudaStreamWaitEvent(0, evEnd, 0);
}

// round 17
// speedup vs baseline: 1.3707x; 1.3707x over previous
#include <cuda_runtime.h>
#include <cuda_bf16.h>
#include <math.h>
#include <stdint.h>

#define BB 64
#define KB 8
#define RR 512
#define HH 1024
#define VV 400
#define V1 401
#define LL 13
#define G4 4096
#define NP 1000
#define SK 4

typedef unsigned long long ull;

// ---------------- persistent scratch -----------------------------------------
__device__ float d_ct[2][RR*HH];
__device__ float d_Gmx[2][RR];
__device__ float d_logp[2][RR];
__device__ int   d_prev[RR];
__device__ int   d_order[RR];
__device__ float d_samples[2][RR*LL];
__device__ float d_outputs[2][RR*LL];
__device__ float d_entplot[BB];
__device__ float d_entelem[BB];
__device__ float d_xW2[BB*G4];
__device__ float d_E[V1*128];
__device__ float d_Gt[V1*G4];
__device__ float d_Gt2[V1*G4];
__device__ float d_lu[NP];
__device__ __nv_bfloat16 d_w2b[2][G4*HH];
__device__ __nv_bfloat16 d_wf2b[2][HH*HH];
__device__ __nv_bfloat16 d_wo2b[2][512*HH];
__device__ __nv_bfloat16 d_h2b[2][RR*HH];
__device__ float d_graw[RR*G4];
__device__ float d_fc1p[SK][RR*HH];
__device__ float d_lpp[SK][RR*VV];
__device__ float d_lpn[RR*VV];
__device__ float d_gm[RR*VV];
__device__ float d_entrow[RR];
__device__ float d_phik[2][BB*KB];
__device__ float d_entbeams[2][BB*KB];
__device__ float d_Ts[BB*KB*NP];
__device__ float d_lseI[BB];
__device__ float d_lseIs[BB*KB];
__device__ float d_lseSS[BB*28];
__device__ float d_logRs[BB*KB];
__device__ float d_logRss[BB*KB*KB];

// ---------------- helpers ------------------------------------------------------
__device__ __forceinline__ float sigmoidf(float x){ return 1.f/(1.f+expf(-x)); }

__device__ __forceinline__ float log1mexp(float x){
    x = fminf(x, -1e-38f);
    if (x > -0.6931472f) return logf(-expm1f(x));
    return log1pf(-expf(x));
}
__device__ __forceinline__ uint32_t smem_u32(const void* p){
    uint32_t a;
    asm("{ .reg .u64 t; cvta.to.shared.u64 t, %1; cvt.u32.u64 %0, t; }" : "=r"(a) : "l"(p));
    return a;
}
__device__ __forceinline__ void ldsm_x4(unsigned* r, uint32_t addr){
    asm volatile("ldmatrix.sync.aligned.m8n8.x4.shared.b16 {%0,%1,%2,%3}, [%4];"
        : "=r"(r[0]), "=r"(r[1]), "=r"(r[2]), "=r"(r[3]) : "r"(addr));
}
__device__ __forceinline__ void ldsm_x2(unsigned* r, uint32_t addr){
    asm volatile("ldmatrix.sync.aligned.m8n8.x2.shared.b16 {%0,%1}, [%2];"
        : "=r"(r[0]), "=r"(r[1]) : "r"(addr));
}
__device__ __forceinline__ void mma_bf16(float* c, const unsigned* a, const unsigned* b){
    asm volatile("mma.sync.aligned.m16n8k16.row.col.f32.bf16.bf16.f32 "
        "{%0,%1,%2,%3}, {%4,%5,%6,%7}, {%8,%9}, {%0,%1,%2,%3};"
        : "+f"(c[0]), "+f"(c[1]), "+f"(c[2]), "+f"(c[3])
        : "r"(a[0]), "r"(a[1]), "r"(a[2]), "r"(a[3]), "r"(b[0]), "r"(b[1]));
}
__device__ __forceinline__ unsigned pkbf2(float a, float b){
    __nv_bfloat162 t; t.x = __float2bfloat16(a); t.y = __float2bfloat16(b);
    return *(unsigned*)&t;
}

// ---------------- init ----------------------------------------------------------
__global__ void init_kernel(const float* __restrict__ W_in_op,
                            const float* __restrict__ b_in_op){
    int idx = blockIdx.x*blockDim.x + threadIdx.x;
    int stride = gridDim.x*blockDim.x;
    for (int i = idx; i < RR;    i += stride){ d_Gmx[0][i]=0.f; d_logp[0][i]=0.f; }
    for (int i = idx; i < RR*LL; i += stride){ d_samples[0][i]=0.f; d_outputs[0][i]=0.f; }
    for (int i = idx; i < BB;    i += stride){ d_entplot[i]=0.f; d_entelem[i]=0.f; }
    for (int i = idx; i < NP;    i += stride) d_lu[i] = logf(((float)i + 0.5f)/(float)NP);
    for (int i = idx; i < V1*128; i += stride){
        int s = i >> 7, m = i & 127;
        d_E[i] = fmaxf(W_in_op[m*V1 + s] + b_in_op[m], 0.f);
    }
}

__global__ void reorder_whh(const float* __restrict__ W){
    int idx = blockIdx.x*blockDim.x + threadIdx.x;
    if (idx >= G4*HH) return;
    int c = idx >> 10, k = idx & 1023;
    int h = c >> 2, g = c & 3;
    float w = W[(size_t)(g*HH + h)*HH + k];
    __nv_bfloat16 b0 = __float2bfloat16(w);
    d_w2b[0][idx] = b0;
    d_w2b[1][idx] = __float2bfloat16(w - __bfloat162float(b0));
}

__global__ void split_fw(const float* __restrict__ W_fc1,
                         const float* __restrict__ W_out){
    int idx = blockIdx.x*blockDim.x + threadIdx.x;
    const int N1 = HH*HH;
    if (idx < N1){
        float w = W_fc1[idx];
        __nv_bfloat16 b0 = __float2bfloat16(w);
        d_wf2b[0][idx] = b0;
        d_wf2b[1][idx] = __float2bfloat16(w - __bfloat162float(b0));
    } else if (idx < N1 + 512*HH){
        int j = idx - N1;
        int row = j >> 10, k = j & 1023;
        float w = (row < VV) ? W_out[(size_t)row*HH + k] : 0.f;
        __nv_bfloat16 b0 = __float2bfloat16(w);
        d_wo2b[0][j] = b0;
        d_wo2b[1][j] = __float2bfloat16(w - __bfloat162float(b0));
    }
}

__global__ void permute_gates(const float* __restrict__ b_ih,
                              const float* __restrict__ b_hh){
    int idx = blockIdx.x*blockDim.x + threadIdx.x;
    if (idx >= (BB+V1)*G4) return;
    int row = idx / G4, c = idx - row*G4;
    int g = c >> 10, h = c & 1023;
    int dstc = 4*h + g;
    if (row < BB){
        size_t off = (size_t)row*G4 + c;
        float v = d_fc1p[0][off] + d_fc1p[1][off] + d_fc1p[2][off] + d_fc1p[3][off]
                + b_ih[c] + b_hh[c];
        d_xW2[row*G4 + dstc] = v;
    } else {
        d_Gt2[(size_t)(row-BB)*G4 + dstc] = d_Gt[(size_t)(row-BB)*G4 + c];
    }
}

// ---------------- setup GEMM (64x64x16 db, scalar) with K-split -------------------
__global__ void __launch_bounds__(256) gemm_db(
    const float* __restrict__ A, int lda,
    const float* __restrict__ B, int ldb,
    float* __restrict__ C, int ldc,
    int M, int N, int K, size_t zC)
{
    A += (size_t)blockIdx.z * K;
    B += (size_t)blockIdx.z * K;
    C += (size_t)blockIdx.z * zC;
    __shared__ float As[2][16][64+4];
    __shared__ float Bs[2][16][64+4];
    const int tid = threadIdx.x;
    const int row0 = blockIdx.y*64, col0 = blockIdx.x*64;
    const int arow = tid >> 2, ak = (tid & 3)*4;
    const int ty = tid >> 4, tx = tid & 15;

    const int ar = row0 + arow, br = col0 + arow;
    float4 a4 = make_float4(0,0,0,0), b4 = make_float4(0,0,0,0);
    if (ar < M) a4 = *(const float4*)(A + (size_t)ar*lda + ak);
    if (br < N) b4 = *(const float4*)(B + (size_t)br*ldb + ak);
    As[0][ak+0][arow]=a4.x; As[0][ak+1][arow]=a4.y; As[0][ak+2][arow]=a4.z; As[0][ak+3][arow]=a4.w;
    Bs[0][ak+0][arow]=b4.x; Bs[0][ak+1][arow]=b4.y; Bs[0][ak+2][arow]=b4.z; Bs[0][ak+3][arow]=b4.w;
    __syncthreads();

    float acc[4][4];
#pragma unroll
    for (int i=0;i<4;i++)
#pragma unroll
        for (int j=0;j<4;j++) acc[i][j]=0.f;

    const int NT = K/16;
    for (int it=0; it<NT; it++){
        int cur = it & 1;
        float4 a4n, b4n;
        if (it+1 < NT){
            int k0 = (it+1)*16;
            a4n = make_float4(0,0,0,0); b4n = make_float4(0,0,0,0);
            if (ar < M) a4n = *(const float4*)(A + (size_t)ar*lda + k0 + ak);
            if (br < N) b4n = *(const float4*)(B + (size_t)br*ldb + k0 + ak);
        }
#pragma unroll
        for (int kk=0; kk<16; kk++){
            float4 ra = *(const float4*)&As[cur][kk][ty*4];
            float4 rb = *(const float4*)&Bs[cur][kk][tx*4];
            float r[4]={ra.x,ra.y,ra.z,ra.w};
            float cb[4]={rb.x,rb.y,rb.z,rb.w};
#pragma unroll
            for (int i=0;i<4;i++)
#pragma unroll
                for (int j=0;j<4;j++) acc[i][j] = fmaf(r[i], cb[j], acc[i][j]);
        }
        if (it+1 < NT){
            int nb = cur^1;
            As[nb][ak+0][arow]=a4n.x; As[nb][ak+1][arow]=a4n.y; As[nb][ak+2][arow]=a4n.z; As[nb][ak+3][arow]=a4n.w;
            Bs[nb][ak+0][arow]=b4n.x; Bs[nb][ak+1][arow]=b4n.y; Bs[nb][ak+2][arow]=b4n.z; Bs[nb][ak+3][arow]=b4n.w;
        }
        __syncthreads();
    }
#pragma unroll
    for (int i=0;i<4;i++){
        int r = row0 + ty*4 + i;
        if (r >= M) continue;
#pragma unroll
        for (int j=0;j<4;j++){
            int c = col0 + tx*4 + j;
            if (c >= N) continue;
            C[(size_t)r*ldc + c] = acc[i][j];
        }
    }
}

// ---------------- generic bf16x2 HMMA NT GEMM (3 products) ------------------------
#define CH_TILE 6144
#define CH_BUF  (4*CH_TILE)
#define GM_DSMEM (2*CH_BUF)

template<int NCH, bool GUARD>
__global__ void __launch_bounds__(256) mma_nt(
    const __nv_bfloat16* __restrict__ A0, const __nv_bfloat16* __restrict__ A1,
    const __nv_bfloat16* __restrict__ B0, const __nv_bfloat16* __restrict__ B1,
    float* __restrict__ Cb, int ldc, size_t cstride)
{
    extern __shared__ char dsm[];
    const int tid = threadIdx.x, w = tid>>5, lane = tid&31;
    const int row0 = blockIdx.y*128, col0 = blockIdx.x*128;
    const int kb = blockIdx.z * (NCH*16);
    const int wr = w>>2, wc = w&3;
    const uint32_t dbase = smem_u32(dsm);
    float* C = Cb + blockIdx.z * cstride;

    const __nv_bfloat16* Asrc[2] = {A0, A1};
    const __nv_bfloat16* Bsrc[2] = {B0, B1};

    int ld_tile[4], ld_row[4], ld_half[4];
    const __nv_bfloat16* ld_src[4];
#pragma unroll
    for (int j=0;j<4;j++){
        int idx = tid + j*256;
        int t = idx >> 8, pos = idx & 255;
        int row = pos >> 1, half = pos & 1;
        ld_tile[j]=t; ld_row[j]=row; ld_half[j]=half;
        if (t < 2) ld_src[j] = Asrc[t]   + (size_t)(row0+row)*HH + kb + half*8;
        else       ld_src[j] = Bsrc[t-2] + (size_t)(col0+row)*HH + kb + half*8;
    }

    float acc[4][4][4];
#pragma unroll
    for (int mi=0;mi<4;mi++)
#pragma unroll
        for (int ni=0;ni<4;ni++)
#pragma unroll
            for (int e=0;e<4;e++) acc[mi][ni][e]=0.f;

    uint4 v[4];
#pragma unroll
    for (int j=0;j<4;j++) v[j] = *(const uint4*)(ld_src[j]);
    {
        char* bp = dsm;
#pragma unroll
        for (int j=0;j<4;j++)
            *(uint4*)(bp + ld_tile[j]*CH_TILE + ld_row[j]*48 + ld_half[j]*16) = v[j];
    }
    __syncthreads();

    const uint32_t a_lm = dbase + (wr*64 + (lane&15))*48 + (lane>>4)*16;
    const uint32_t b_lm = dbase + (wc*32 + (lane&7))*48 + ((lane>>3)&1)*16;

    for (int kc = 0; kc < NCH; kc++){
        if (kc+1 < NCH){
#pragma unroll
            for (int j=0;j<4;j++) v[j] = *(const uint4*)(ld_src[j] + (kc+1)*16);
        }
        const uint32_t bb = (kc&1)*CH_BUF;

        unsigned Bf[2][4][2];
#pragma unroll
        for (int s=0;s<2;s++)
#pragma unroll
            for (int ni=0;ni<4;ni++)
                ldsm_x2(Bf[s][ni], b_lm + bb + (2+s)*CH_TILE + ni*8*48);

#pragma unroll
        for (int s=0;s<2;s++){
            unsigned Af[4][4];
#pragma unroll
            for (int mi=0;mi<4;mi++)
                ldsm_x4(Af[mi], a_lm + bb + s*CH_TILE + mi*16*48);
            const int nb = (s==0) ? 2 : 1;
#pragma unroll
            for (int jb=0;jb<2;jb++){
                if (jb >= nb) break;
#pragma unroll
                for (int mi=0;mi<4;mi++)
#pragma unroll
                    for (int ni=0;ni<4;ni++)
                        mma_bf16(acc[mi][ni], Af[mi], Bf[jb][ni]);
            }
        }

        if (kc+1 < NCH){
            char* bp = dsm + ((kc+1)&1)*CH_BUF;
#pragma unroll
            for (int j=0;j<4;j++)
                *(uint4*)(bp + ld_tile[j]*CH_TILE + ld_row[j]*48 + ld_half[j]*16) = v[j];
        }
        __syncthreads();
    }

#pragma unroll
    for (int mi=0;mi<4;mi++)
#pragma unroll
        for (int ni=0;ni<4;ni++){
            int rl = wr*64 + mi*16 + (lane>>2);
            int cl = wc*32 + ni*8 + 2*(lane&3);
            if (GUARD && col0+cl >= ldc) continue;
            float2 p0 = make_float2(acc[mi][ni][0], acc[mi][ni][1]);
            float2 p1 = make_float2(acc[mi][ni][2], acc[mi][ni][3]);
            *(float2*)&C[(size_t)(row0+rl)*ldc   + col0 + cl] = p0;
            *(float2*)&C[(size_t)(row0+rl+8)*ldc + col0 + cl] = p1;
        }
}

// ---------------- out GEMM with fused hd ------------------------------------------
__global__ void __launch_bounds__(256) out_fused(const float* __restrict__ b_fc1){
    extern __shared__ char dsm[];
    const int tid = threadIdx.x, w = tid>>5, lane = tid&31;
    const int row0 = blockIdx.y*128, col0 = blockIdx.x*128;
    const int kb = blockIdx.z * 256;
    const int wr = w>>2, wc = w&3;
    const uint32_t dbase = smem_u32(dsm);
    float* C = d_lpp[blockIdx.z];

    const int arow_ = tid >> 1, half = tid & 1;
    const size_t aoffb = (size_t)(row0+arow_)*HH + kb + half*8;
    const __nv_bfloat16* bsrc0 = d_wo2b[0] + (size_t)(col0+arow_)*HH + kb + half*8;
    const __nv_bfloat16* bsrc1 = d_wo2b[1] + (size_t)(col0+arow_)*HH + kb + half*8;
    const uint32_t st_a = arow_*48 + half*16;

    auto computeA = [&](int kc, uint4 &lo, uint4 &hi){
        size_t off = aoffb + kc*16;
        int bix = kb + kc*16 + half*8;
        float x[8];
        {
            float4 p0=*(const float4*)&d_fc1p[0][off], p1=*(const float4*)&d_fc1p[1][off];
            float4 p2=*(const float4*)&d_fc1p[2][off], p3=*(const float4*)&d_fc1p[3][off];
            float4 bf=*(const float4*)&b_fc1[bix];
            x[0]=fmaxf(p0.x+p1.x+p2.x+p3.x+bf.x,0.f);
            x[1]=fmaxf(p0.y+p1.y+p2.y+p3.y+bf.y,0.f);
            x[2]=fmaxf(p0.z+p1.z+p2.z+p3.z+bf.z,0.f);
            x[3]=fmaxf(p0.w+p1.w+p2.w+p3.w+bf.w,0.f);
        }
        {
            float4 p0=*(const float4*)&d_fc1p[0][off+4], p1=*(const float4*)&d_fc1p[1][off+4];
            float4 p2=*(const float4*)&d_fc1p[2][off+4], p3=*(const float4*)&d_fc1p[3][off+4];
            float4 bf=*(const float4*)&b_fc1[bix+4];
            x[4]=fmaxf(p0.x+p1.x+p2.x+p3.x+bf.x,0.f);
            x[5]=fmaxf(p0.y+p1.y+p2.y+p3.y+bf.y,0.f);
            x[6]=fmaxf(p0.z+p1.z+p2.z+p3.z+bf.z,0.f);
            x[7]=fmaxf(p0.w+p1.w+p2.w+p3.w+bf.w,0.f);
        }
        unsigned lo_[4], hi_[4];
#pragma unroll
        for (int e=0;e<4;e++){
            float a = x[2*e], b = x[2*e+1];
            __nv_bfloat16 la = __float2bfloat16(a), lb = __float2bfloat16(b);
            lo_[e] = pkbf2(a, b);
            hi_[e] = pkbf2(a - __bfloat162float(la), b - __bfloat162float(lb));
        }
        lo = make_uint4(lo_[0], lo_[1], lo_[2], lo_[3]);
        hi = make_uint4(hi_[0], hi_[1], hi_[2], hi_[3]);
    };

    float acc[4][4][4];
#pragma unroll
    for (int mi=0;mi<4;mi++)
#pragma unroll
        for (int ni=0;ni<4;ni++)
#pragma unroll
            for (int e=0;e<4;e++) acc[mi][ni][e]=0.f;

    uint4 aLo, aHi, vB0, vB1;
    computeA(0, aLo, aHi);
    vB0 = *(const uint4*)bsrc0;
    vB1 = *(const uint4*)bsrc1;
    {
        char* bp = dsm;
        *(uint4*)(bp + 0*CH_TILE + st_a) = aLo;
        *(uint4*)(bp + 1*CH_TILE + st_a) = aHi;
        *(uint4*)(bp + 2*CH_TILE + st_a) = vB0;
        *(uint4*)(bp + 3*CH_TILE + st_a) = vB1;
    }
    __syncthreads();

    const uint32_t a_lm = dbase + (wr*64 + (lane&15))*48 + (lane>>4)*16;
    const uint32_t b_lm = dbase + (wc*32 + (lane&7))*48 + ((lane>>3)&1)*16;

    for (int kc = 0; kc < 16; kc++){
        if (kc+1 < 16){
            computeA(kc+1, aLo, aHi);
            vB0 = *(const uint4*)(bsrc0 + (kc+1)*16);
            vB1 = *(const uint4*)(bsrc1 + (kc+1)*16);
        }
        const uint32_t bb = (kc&1)*CH_BUF;

        unsigned Bf[2][4][2];
#pragma unroll
        for (int s=0;s<2;s++)
#pragma unroll
            for (int ni=0;ni<4;ni++)
                ldsm_x2(Bf[s][ni], b_lm + bb + (2+s)*CH_TILE + ni*8*48);

#pragma unroll
        for (int s=0;s<2;s++){
            unsigned Af[4][4];
#pragma unroll
            for (int mi=0;mi<4;mi++)
                ldsm_x4(Af[mi], a_lm + bb + s*CH_TILE + mi*16*48);
            const int nb = (s==0) ? 2 : 1;
#pragma unroll
            for (int jb=0;jb<2;jb++){
                if (jb >= nb) break;
#pragma unroll
                for (int mi=0;mi<4;mi++)
#pragma unroll
                    for (int ni=0;ni<4;ni++)
                        mma_bf16(acc[mi][ni], Af[mi], Bf[jb][ni]);
            }
        }

        if (kc+1 < 16){
            char* bp = dsm + ((kc+1)&1)*CH_BUF;
            *(uint4*)(bp + 0*CH_TILE + st_a) = aLo;
            *(uint4*)(bp + 1*CH_TILE + st_a) = aHi;
            *(uint4*)(bp + 2*CH_TILE + st_a) = vB0;
            *(uint4*)(bp + 3*CH_TILE + st_a) = vB1;
        }
        __syncthreads();
    }

#pragma unroll
    for (int mi=0;mi<4;mi++)
#pragma unroll
        for (int ni=0;ni<4;ni++){
            int rl = wr*64 + mi*16 + (lane>>2);
            int cl = wc*32 + ni*8 + 2*(lane&3);
            if (col0+cl >= VV) continue;
            float2 p0 = make_float2(acc[mi][ni][0], acc[mi][ni][1]);
            float2 p1 = make_float2(acc[mi][ni][2], acc[mi][ni][3]);
            *(float2*)&C[(size_t)(row0+rl)*VV   + col0 + cl] = p0;
            *(float2*)&C[(size_t)(row0+rl+8)*VV + col0 + cl] = p1;
        }
}

// ---------------- LSTM elementwise -------------------------------------------------
__global__ void __launch_bounds__(256) lstm_elem(int t, int cur){
    const int r = blockIdx.x, tid = threadIdx.x;
    const int prv = cur^1;
    const int b = r & 63;
    int o, pv;
    if (t == 0){ o = r; pv = VV; } else { o = d_order[r]; pv = d_prev[r]; }
    const float4* gr = (const float4*)(d_graw + (size_t)o*G4);
    const float4* xw = (const float4*)(d_xW2 + (size_t)b*G4);
    const float4* gt = (const float4*)(d_Gt2 + (size_t)pv*G4);
    const float* cpf = d_ct[prv] + (size_t)o*HH;
    float* cf = d_ct[cur] + (size_t)r*HH;
#pragma unroll
    for (int q=0;q<4;q++){
        int u = tid + q*256;
        float4 g = (t==0) ? make_float4(0,0,0,0) : gr[u];
        float4 x = xw[u];
        float4 G = gt[u];
        float ig = g.x + x.x + G.x;
        float fg = g.y + x.y + G.y;
        float gg = g.z + x.z + G.z;
        float og = g.w + x.w + G.w;
        float cold = (t==0) ? 0.f : cpf[u];
        float cn = sigmoidf(fg)*cold + sigmoidf(ig)*tanhf(gg);
        float hn = sigmoidf(og)*tanhf(cn);
        cf[u] = cn;
        __nv_bfloat16 s0 = __float2bfloat16(hn);
        d_h2b[0][(size_t)r*HH + u] = s0;
        d_h2b[1][(size_t)r*HH + u] = __float2bfloat16(hn - __bfloat162float(s0));
    }
}

// ---------------- A1: per-row softmax + entropy + gumbel-with-max -----------------
__global__ void __launch_bounds__(128) rowsoft(const float* __restrict__ gu,
                                               const float* __restrict__ b_out,
                                               int t, int cur){
    const int r = blockIdx.x, tid = threadIdx.x;
    __shared__ float red[128];
    const size_t rb = (size_t)r*VV;

    float lv[4];
#pragma unroll
    for (int ii=0; ii<4; ii++){
        int v = tid + ii*128;
        lv[ii] = (v < VV)
            ? (d_lpp[0][rb+v] + d_lpp[1][rb+v] + d_lpp[2][rb+v] + d_lpp[3][rb+v] + b_out[v])
            : -INFINITY;
    }
    float m = fmaxf(fmaxf(lv[0],lv[1]), fmaxf(lv[2],lv[3]));
    red[tid] = m; __syncthreads();
    for (int off=64; off; off>>=1){ if (tid<off) red[tid]=fmaxf(red[tid],red[tid+off]); __syncthreads(); }
    m = red[0]; __syncthreads();

    float s = 0.f;
#pragma unroll
    for (int ii=0; ii<4; ii++){ int v = tid+ii*128; if (v < VV) s += expf(lv[ii]-m); }
    red[tid] = s; __syncthreads();
    for (int off=64; off; off>>=1){ if (tid<off) red[tid]+=red[tid+off]; __syncthreads(); }
    float lse = m + logf(red[0]); __syncthreads();

    float lpr = d_logp[cur][r];
    float Gr  = d_Gmx[cur][r];
    const float* u = gu + ((size_t)t*RR + r)*VV;
    float ent = 0.f, zm = -INFINITY;
    float gv[4];
#pragma unroll
    for (int ii=0; ii<4; ii++){
        int v = tid + ii*128;
        if (v >= VV){ gv[ii] = -INFINITY; continue; }
        float l = lv[ii]-lse;
        d_lpn[rb+v] = l;
        ent += l*expf(l);
        float gmb = -logf(-logf(u[v]*(1.f-2e-7f)+1e-7f));
        float gph = l + lpr + gmb;
        gv[ii] = gph;
        zm = fmaxf(zm, gph);
    }
    red[tid] = ent; __syncthreads();
    for (int off=64; off; off>>=1){ if (tid<off) red[tid]+=red[tid+off]; __syncthreads(); }
    if (tid==0) d_entrow[r] = red[0];
    __syncthreads();
    red[tid] = zm; __syncthreads();
    for (int off=64; off; off>>=1){ if (tid<off) red[tid]=fmaxf(red[tid],red[tid+off]); __syncthreads(); }
    float Z = red[0];
#pragma unroll
    for (int ii=0; ii<4; ii++){
        int v = tid + ii*128;
        if (v >= VV) continue;
        float gph = gv[ii];
        float vv = Gr - gph + log1mexp(gph - Z);
        d_gm[rb+v] = Gr - fmaxf(vv,0.f) - log1pf(expf(-fabsf(vv)));
    }
}

// ---------------- A2: top-k + gather ----------------------------------------------
__global__ void __launch_bounds__(256) topsel(int t, int cur){
    __shared__ float cv_s[64];
    __shared__ int   ci_s[64];
    __shared__ float gvalS[KB];
    __shared__ int   ordS[KB], snewS[KB];

    const int i = blockIdx.x, tid = threadIdx.x;
    const int lane = tid & 31, w = tid >> 5;
    const int r = w*BB + i;
    const size_t rb = (size_t)r*VV;
    const int ph = t & 1;

    float lv[13];
#pragma unroll
    for (int ii=0; ii<13; ii++){
        int v = lane + ii*32;
        lv[ii] = (v < VV && !(t==0 && w>0)) ? d_gm[rb+v] : -INFINITY;
    }

    for (int round=0; round<KB; round++){
        float bv = -INFINITY; int bi = 0x7fffffff;
#pragma unroll
        for (int ii=0; ii<13; ii++){
            int v = lane + ii*32;
            if (v >= VV) continue;
            float x = lv[ii]; int fi = w*VV + v;
            if (x > bv || (x == bv && fi < bi)){ bv = x; bi = fi; }
        }
#pragma unroll
        for (int off=16; off; off>>=1){
            float bv2 = __shfl_xor_sync(0xffffffffu, bv, off);
            int   bi2 = __shfl_xor_sync(0xffffffffu, bi, off);
            if (bv2 > bv || (bv2 == bv && bi2 < bi)){ bv = bv2; bi = bi2; }
        }
        int vwin = bi - w*VV;
        if (vwin >= 0 && vwin < VV && (vwin & 31) == lane) lv[vwin >> 5] = -INFINITY;
        if (lane == 0){ cv_s[w*KB + round] = bv; ci_s[w*KB + round] = bi; }
    }
    __syncthreads();

    if (w == 0){
        float c0 = cv_s[lane], c1 = cv_s[lane+32];
        int   i0 = ci_s[lane], i1 = ci_s[lane+32];
        for (int round=0; round<KB; round++){
            float bv; int bi;
            if (c0 > c1 || (c0 == c1 && i0 < i1)){ bv = c0; bi = i0; }
            else                                 { bv = c1; bi = i1; }
#pragma unroll
            for (int off=16; off; off>>=1){
                float bv2 = __shfl_xor_sync(0xffffffffu, bv, off);
                int   bi2 = __shfl_xor_sync(0xffffffffu, bi, off);
                if (bv2 > bv || (bv2 == bv && bi2 < bi)){ bv = bv2; bi = bi2; }
            }
            if (i0 == bi) c0 = -INFINITY;
            if (i1 == bi) c1 = -INFINITY;
            if (lane == 0){
                gvalS[round] = bv;
                ordS[round]  = bi / VV;
                snewS[round] = bi % VV;
            }
        }
    }
    __syncthreads();

    const int nxt = cur^1;
    for (int idx=tid; idx<KB*LL; idx+=256){
        int j = idx/LL, tt = idx - j*LL;
        if (tt == t) continue;
        int rn = j*BB+i, o = ordS[j]*BB+i;
        d_samples[nxt][rn*LL+tt] = d_samples[cur][o*LL+tt];
        d_outputs[nxt][rn*LL+tt] = d_outputs[cur][o*LL+tt];
    }
    if (tid < KB){
        int j = tid, rn = j*BB+i, o = ordS[j]*BB+i, sv = snewS[j];
        float lpv = d_lpn[(size_t)o*VV + sv];
        float nl  = d_logp[cur][o] + lpv;
        d_samples[nxt][rn*LL+t] = (float)sv;
        d_outputs[nxt][rn*LL+t] = lpv;
        d_logp[nxt][rn] = nl;
        d_Gmx[nxt][rn]  = gvalS[j];
        d_prev[rn]  = sv;
        d_order[rn] = o;
        d_phik[ph][i*KB+j]     = nl;
        d_entbeams[ph][i*KB+j] = d_entrow[o];
    }
}

// ---------------- B1: Ts precompute ------------------------------------------------
__global__ void __launch_bounds__(256) tsprep(int ph){
    const int j = blockIdx.x, i = blockIdx.y, tid = threadIdx.x;
    const float p = expf(d_phik[ph][i*KB+j]);
    float* dst = d_Ts + ((size_t)i*KB + j)*NP;
    for (int n = tid; n < NP; n += 256)
        dst[n] = log1mexp(p * d_lu[n]);
}

// ---------------- warp LSE ---------------------------------------------------------
__device__ __forceinline__ float warpLSE(const float* __restrict__ base,
                                         const float* __restrict__ t1,
                                         const float* __restrict__ t2){
    int lane = threadIdx.x & 31;
    float m = -INFINITY, s = 0.f;
    for (int n = lane; n < NP; n += 32){
        float x = base[n];
        if (t1) x -= t1[n];
        if (t2) x -= t2[n];
        if (x > m){ s = s*expf(m-x) + 1.f; m = x; } else s += expf(x-m);
    }
#pragma unroll
    for (int off=16; off; off>>=1){
        float m2 = __shfl_xor_sync(0xffffffffu, m, off);
        float s2 = __shfl_xor_sync(0xffffffffu, s, off);
        float mm = fmaxf(m, m2);
        s = s*expf(m-mm) + s2*expf(m2-mm);
        m = mm;
    }
    return m + logf(s);
}

// ---------------- B2: distributed LSEs ---------------------------------------------
__global__ void __launch_bounds__(256) logR_lse(int ph){
    __shared__ float Ts_s[KB*NP];
    __shared__ float base_s[NP];
    const int g = blockIdx.x, i = blockIdx.y, tid = threadIdx.x;
    const int lane = tid & 31, w = tid >> 5;

    for (int idx = tid; idx < KB*NP; idx += 256)
        Ts_s[idx] = d_Ts[(size_t)i*KB*NP + idx];
    float pS = 0.f;
#pragma unroll
    for (int j=0;j<KB;j++) pS += expf(d_phik[ph][i*KB+j]);
    __syncthreads();
    for (int n = tid; n < NP; n += 256){
        float bs = -pS*d_lu[n];
#pragma unroll
        for (int j=0;j<KB;j++) bs += Ts_s[j*NP+n];
        base_s[n] = bs;
    }
    __syncthreads();

    const int q = g*8 + w;
    if (q < 37){
        const float *t1 = nullptr, *t2 = nullptr;
        int a = 0, b = 0;
        if (q >= 1 && q <= 8){ t1 = Ts_s + (q-1)*NP; }
        else if (q >= 9){
            int pp = q-9, rem = pp;
            while (rem >= 7 - a){ rem -= (7 - a); a++; }
            b = a + 1 + rem;
            t1 = Ts_s + a*NP; t2 = Ts_s + b*NP;
        }
        float res = warpLSE(base_s, t1, t2);
        if (lane == 0){
            if (q == 0)      d_lseI[i] = res;
            else if (q <= 8) d_lseIs[i*KB + q-1] = res;
            else             d_lseSS[i*28 + (q-9)] = res;
        }
    }
}

// ---------------- B3: finalize log_R + entropy accumulation ------------------------
__global__ void __launch_bounds__(32) logR_fin(int ph){
    const int i = blockIdx.x, tid = threadIdx.x;
    float logI = d_lseI[i];
    if (tid < KB) d_logRs[i*KB+tid] = d_lseIs[i*KB+tid] - logI;
    if (tid < 28){
        int a = 0, rem = tid;
        while (rem >= 7 - a){ rem -= (7 - a); a++; }
        int b = a + 1 + rem;
        float lss = d_lseSS[i*28+tid];
        d_logRss[i*64 + a*8 + b] = lss - d_lseIs[i*KB+a];
        d_logRss[i*64 + b*8 + a] = lss - d_lseIs[i*KB+b];
    }
    if (tid < KB) d_logRss[i*64 + tid*9] = 0.f;
    if (tid == 0){
        float Wsum = 0.f, ws = 0.f;
#pragma unroll
        for (int j=0;j<KB;j++){
            float wq = expf(d_phik[ph][i*KB+j] + d_lseIs[i*KB+j] - logI);
            Wsum += wq;
            ws   += wq * d_entbeams[ph][i*KB+j];
        }
        d_entplot[i] += ws;
        d_entelem[i] += ws / Wsum;
    }
}

// ---------------- output assembly ---------------------------------------------------
__global__ void finalize_kernel(float* __restrict__ out, int out_size){
    int idx = blockIdx.x*blockDim.x + threadIdx.x;
    if (idx >= out_size || idx >= 18560) return;
    const int FIN = LL & 1;
    if (idx < 6656){
        int i = idx/104, rem = idx%104, j = rem/13, tt = rem%13;
        out[idx] = d_outputs[FIN][(j*BB+i)*LL + tt];
    } else if (idx < 13312){
        int q = idx - 6656;
        int i = q/104, rem = q%104, j = rem/13, tt = rem%13;
        out[idx] = d_samples[FIN][(j*BB+i)*LL + tt];
    } else if (idx < 13376){
        out[idx] = d_entelem[idx-13312];
    } else if (idx < 13888){
        out[idx] = d_logRs[idx-13376];
    } else if (idx < 17984){
        out[idx] = d_logRss[idx-13888];
    } else if (idx < 18496){
        out[idx] = d_phik[(LL-1)&1][idx-17984];
    } else {
        out[idx] = d_entplot[idx-18496];
    }
}

// ---------------- host driver ---------------------------------------------------------
extern "C" void kernel_launch(void* const* d_in, const int* in_sizes, int n_in,
                              void* d_out, int out_size){
    const float* x_feat  = (const float*)d_in[0];
    const float* W_in_op = (const float*)d_in[1];
    const float* b_in_op = (const float*)d_in[2];
    const float* W_ih    = (const float*)d_in[3];
    const float* W_hh    = (const float*)d_in[4];
    const float* b_ih    = (const float*)d_in[5];
    const float* b_hh    = (const float*)d_in[6];
    const float* W_fc1   = (const float*)d_in[7];
    const float* b_fc1   = (const float*)d_in[8];
    const float* W_out   = (const float*)d_in[9];
    const float* b_out   = (const float*)d_in[10];
    const float* gu      = (const float*)d_in[11];
    (void)in_sizes; (void)n_in;

    void* tmp;
    cudaGetSymbolAddress(&tmp, d_E);     float* p_E   = (float*)tmp;
    cudaGetSymbolAddress(&tmp, d_Gt);    float* p_Gt  = (float*)tmp;
    cudaGetSymbolAddress(&tmp, d_h2b);   __nv_bfloat16* p_h2b = (__nv_bfloat16*)tmp;
    cudaGetSymbolAddress(&tmp, d_w2b);   __nv_bfloat16* p_w2b = (__nv_bfloat16*)tmp;
    cudaGetSymbolAddress(&tmp, d_wf2b);  __nv_bfloat16* p_wf  = (__nv_bfloat16*)tmp;
    cudaGetSymbolAddress(&tmp, d_graw);  float* p_graw = (float*)tmp;
    cudaGetSymbolAddress(&tmp, d_fc1p);  float* p_fc1p = (float*)tmp;

    static cudaStream_t s1 = nullptr, s2 = nullptr;
    static cudaEvent_t ev0=nullptr, evA=nullptr, evB=nullptr, evW=nullptr,
                       evE=nullptr, evEnd=nullptr;
    if (s1 == nullptr){
        cudaStreamCreateWithFlags(&s1, cudaStreamNonBlocking);
        cudaStreamCreateWithFlags(&s2, cudaStreamNonBlocking);
        cudaEventCreateWithFlags(&ev0, cudaEventDisableTiming);
        cudaEventCreateWithFlags(&evA, cudaEventDisableTiming);
        cudaEventCreateWithFlags(&evB, cudaEventDisableTiming);
        cudaEventCreateWithFlags(&evW, cudaEventDisableTiming);
        cudaEventCreateWithFlags(&evE, cudaEventDisableTiming);
        cudaEventCreateWithFlags(&evEnd, cudaEventDisableTiming);
        cudaFuncSetAttribute(mma_nt<64,false>, cudaFuncAttributeMaxDynamicSharedMemorySize, GM_DSMEM);
        cudaFuncSetAttribute(mma_nt<16,false>, cudaFuncAttributeMaxDynamicSharedMemorySize, GM_DSMEM);
        cudaFuncSetAttribute(out_fused, cudaFuncAttributeMaxDynamicSharedMemorySize, GM_DSMEM);
    }

    cudaEventRecord(ev0, 0);
    cudaStreamWaitEvent(s1, ev0, 0);
    cudaStreamWaitEvent(s2, ev0, 0);

    // s1: init (produces d_E, d_lu) then xW partials
    init_kernel<<<256,256,0,s1>>>(W_in_op, b_in_op);
    cudaEventRecord(evE, s1);
    gemm_db<<<dim3(64,1,SK),256,0,s1>>>(x_feat,1024, W_ih,1152,
                                        p_fc1p, G4, BB, G4, 256, (size_t)RR*HH);

    // s2: weight splits + Gt GEMM (needs d_E)
    reorder_whh<<<(G4*HH+255)/256, 256, 0, s2>>>(W_hh);
    split_fw<<<((HH*HH + 512*HH)+255)/256, 256, 0, s2>>>(W_fc1, W_out);
    cudaStreamWaitEvent(s2, evE, 0);
    gemm_db<<<dim3(64,7,1),256,0,s2>>>(p_E,128, W_ih+1024,1152,
                                       p_Gt, G4, V1, G4, 128, 0);
    cudaEventRecord(evW, s2);

    cudaStreamWaitEvent(s1, evW, 0);
    permute_gates<<<((BB+V1)*G4+255)/256,256,0,s1>>>(b_ih, b_hh);

    for (int t = 0; t < LL; t++){
        int cur = t & 1;
        const bool t0 = (t == 0);

        lstm_elem<<<RR,256,0,s1>>>(t, cur);

        if (t < LL-1){
            cudaEventRecord(evA, s1);
            cudaStreamWaitEvent(s2, evA, 0);
            if (t0)
                mma_nt<64,false><<<dim3(32,1,1),256,GM_DSMEM,s2>>>(
                    p_h2b, p_h2b + (size_t)RR*HH,
                    p_w2b, p_w2b + (size_t)G4*HH,
                    p_graw, G4, 0);
            else
                mma_nt<64,false><<<dim3(32,4,1),256,GM_DSMEM,s2>>>(
                    p_h2b, p_h2b + (size_t)RR*HH,
                    p_w2b, p_w2b + (size_t)G4*HH,
                    p_graw, G4, 0);
            cudaEventRecord(evB, s2);
        }

        // t=0: only batch rows [0,64) reachable by the masked top-k -> shrink grids
        mma_nt<16,false><<<dim3(8, t0?1:4, SK),256,GM_DSMEM,s1>>>(
            p_h2b, p_h2b + (size_t)RR*HH,
            p_wf,  p_wf  + (size_t)HH*HH,
            p_fc1p, HH, (size_t)RR*HH);
        out_fused<<<dim3(4, t0?1:4, SK),256,GM_DSMEM,s1>>>(b_fc1);
        rowsoft<<<t0?BB:RR,128,0,s1>>>(gu, b_out, t, cur);
        topsel<<<BB,256,0,s1>>>(t, cur);
        tsprep<<<dim3(KB,BB),256,0,s1>>>(cur);
        logR_lse<<<dim3(5,BB),256,0,s1>>>(cur);
        logR_fin<<<BB,32,0,s1>>>(cur);

        if (t < LL-1){
            cudaStreamWaitEvent(s1, evB, 0);
        }
    }

    finalize_kernel<<<(18560+255)/256,256,0,s1>>>((float*)d_out, out_size);
    cudaEventRecord(evEnd, s1);
    cudaStreamWaitEvent(0, evEnd, 0);
}